// round 1
// baseline (speedup 1.0000x reference)
#include <cuda_runtime.h>

// param_distance: K=8, B=32, N=4096, D=64
// row = (b,n) flattened, BN = 131072
// out[row] = agg[argmin_k sum_d |t[row,d]-agg[k,row,d]|, row, 0]
//
// Warp-per-row: lane l holds float2 covering d = 2l, 2l+1 (D=64 -> 32 lanes * 2).
// All 8 candidate rows are loaded up front (MLP=9 per warp), then 8 butterfly
// reductions pick the argmin with first-index tie-break (strict <, ascending k).

__global__ __launch_bounds__(256, 8)
void param_distance_kernel(const float* __restrict__ tensor,
                           const float* __restrict__ agg,
                           float* __restrict__ out,
                           int BN)
{
    const int warps_per_block = blockDim.x >> 5;
    const int row  = blockIdx.x * warps_per_block + (threadIdx.x >> 5);
    const int lane = threadIdx.x & 31;
    if (row >= BN) return;

    const size_t rbase   = (size_t)row * 64;
    const size_t kstride = (size_t)BN * 64;

    // tensor row slice for this lane (fully coalesced 256B warp load)
    const float2 tv = *reinterpret_cast<const float2*>(tensor + rbase + lane * 2);

    // batch all 8 candidate loads for max MLP
    float2 av[8];
#pragma unroll
    for (int k = 0; k < 8; ++k) {
        av[k] = *reinterpret_cast<const float2*>(agg + (size_t)k * kstride + rbase + lane * 2);
    }

    float best  = 3.402823466e38f;
    float bestv = 0.0f;

#pragma unroll
    for (int k = 0; k < 8; ++k) {
        float p = fabsf(tv.x - av[k].x) + fabsf(tv.y - av[k].y);
        // full butterfly: every lane ends with the row L1 distance
#pragma unroll
        for (int off = 16; off > 0; off >>= 1)
            p += __shfl_xor_sync(0xFFFFFFFFu, p, off);
        // feature element 0 of candidate k lives in lane 0's av[k].x
        const float a0 = __shfl_sync(0xFFFFFFFFu, av[k].x, 0);
        if (p < best) { best = p; bestv = a0; }  // strict < => first-min tie-break
    }

    if (lane == 0) out[row] = bestv;
}

extern "C" void kernel_launch(void* const* d_in, const int* in_sizes, int n_in,
                              void* d_out, int out_size)
{
    const float* tensor = (const float*)d_in[0];   // [B, N, D] fp32
    const float* agg    = (const float*)d_in[1];   // [K, B, N, D] fp32
    float* out          = (float*)d_out;           // [1, B, N, 1] fp32

    const int D  = 64;
    const int BN = in_sizes[0] / D;                // 131072

    const int threads = 256;                       // 8 warps -> 8 rows per block
    const int rows_per_block = threads / 32;
    const int blocks = (BN + rows_per_block - 1) / rows_per_block;

    param_distance_kernel<<<blocks, threads>>>(tensor, agg, out, BN);
}